// round 1
// baseline (speedup 1.0000x reference)
#include <cuda_runtime.h>
#include <math.h>

#define C_DIM 128
#define S_DIM 4096
#define H_DIM 16
#define W_DIM 11
#define HW 176          // H_DIM * W_DIM
#define B_SEG 32
#define O_DIM 256
#define OTILE 32
#define PART_LEN 44     // 4 rows * 11
#define GEM_EPS 1e-6f

// scratch: pooled[b][c][hw]
__device__ float g_pooled[B_SEG * C_DIM * HW];

// ---------------------------------------------------------------------------
// Kernel 1: ragged segment max.
// One block per (b, c). The region x[c, s0:s1, :, :] is fully contiguous
// (s-stride == HW). Thread t owns column hw=t and scans frames, 4-way
// unrolled for MLP. 192 threads (6 warps), 176 active.
// ---------------------------------------------------------------------------
__global__ void __launch_bounds__(192) seg_max_kernel(
    const float* __restrict__ x, const int* __restrict__ seqL)
{
    int blk = blockIdx.x;
    int b = blk & (B_SEG - 1);
    int c = blk >> 5;

    __shared__ int sh[2];
    if (threadIdx.x == 0) {
        int s0 = 0;
        for (int i = 0; i < b; i++) s0 += seqL[i];
        sh[0] = s0;
        sh[1] = seqL[b];
    }
    __syncthreads();

    int hw = threadIdx.x;
    if (hw >= HW) return;

    int s0  = sh[0];
    int len = sh[1];

    const float* base = x + (size_t)c * (S_DIM * HW) + (size_t)s0 * HW + hw;

    float m = -3.402823466e38f;
    int s = 0;
    for (; s + 4 <= len; s += 4) {
        float a0 = base[(size_t)(s + 0) * HW];
        float a1 = base[(size_t)(s + 1) * HW];
        float a2 = base[(size_t)(s + 2) * HW];
        float a3 = base[(size_t)(s + 3) * HW];
        m = fmaxf(m, fmaxf(fmaxf(a0, a1), fmaxf(a2, a3)));
    }
    for (; s < len; s++) {
        m = fmaxf(m, base[(size_t)s * HW]);
    }

    g_pooled[(b * C_DIM + c) * HW + hw] = m;
}

// ---------------------------------------------------------------------------
// Kernel 2: fused 1x1 conv + GeM.
// Grid: (O_DIM/OTILE, B_SEG). Each block: load W tile [C][OTILE] into smem,
// thread hw computes y[o0..o0+31][hw] via 32 accumulators, then
// exp2(p*log2(clip(y))) into smem; finally 128 threads reduce 44-element
// parts and apply the 1/p root.
// ---------------------------------------------------------------------------
__global__ void __launch_bounds__(192) conv_gem_kernel(
    const float* __restrict__ Wmat, const float* __restrict__ p,
    float* __restrict__ out)
{
    __shared__ float ws[C_DIM * OTILE];   // [c][j], 16 KB
    __shared__ float ypow[OTILE * HW];    // [j][hw], 22 KB
    __shared__ float pp[4];

    int b  = blockIdx.y;
    int o0 = blockIdx.x * OTILE;
    int tid = threadIdx.x;

    if (tid < 4) pp[tid] = p[tid];
    for (int i = tid; i < C_DIM * OTILE; i += blockDim.x) {
        int cc = i >> 5;
        int j  = i & (OTILE - 1);
        ws[i] = Wmat[(o0 + j) * C_DIM + cc];
    }
    __syncthreads();

    int hw = tid;
    if (hw < HW) {
        float acc[OTILE];
        #pragma unroll
        for (int j = 0; j < OTILE; j++) acc[j] = 0.0f;

        const float* pb = g_pooled + (size_t)b * C_DIM * HW + hw;
        #pragma unroll 2
        for (int cc = 0; cc < C_DIM; cc++) {
            float pv = pb[(size_t)cc * HW];
            const float4* w4 = (const float4*)(ws + cc * OTILE);
            #pragma unroll
            for (int jj = 0; jj < OTILE / 4; jj++) {
                float4 wv = w4[jj];
                acc[jj * 4 + 0] += pv * wv.x;
                acc[jj * 4 + 1] += pv * wv.y;
                acc[jj * 4 + 2] += pv * wv.z;
                acc[jj * 4 + 3] += pv * wv.w;
            }
        }

        int part = hw / PART_LEN;       // 0..3 (44 = 4 rows * 11 cols)
        float pe = pp[part];
        #pragma unroll
        for (int j = 0; j < OTILE; j++) {
            float v = fmaxf(acc[j], GEM_EPS);
            ypow[j * HW + hw] = exp2f(pe * __log2f(v));
        }
    }
    __syncthreads();

    // 128 threads: one per (j, part)
    if (tid < OTILE * 4) {
        int j    = tid >> 2;
        int part = tid & 3;
        const float* yp = ypow + j * HW + part * PART_LEN;
        float sum = 0.0f;
        #pragma unroll
        for (int k = 0; k < PART_LEN; k++) sum += yp[k];
        float pe = pp[part];
        float mean = sum * (1.0f / (float)PART_LEN);
        float g = (mean > 0.0f) ? exp2f(__log2f(mean) / pe) : 0.0f;
        out[((size_t)b * O_DIM + o0 + j) * 4 + part] = g;
    }
}

extern "C" void kernel_launch(void* const* d_in, const int* in_sizes, int n_in,
                              void* d_out, int out_size)
{
    const float* x    = (const float*)d_in[0];
    const int*   seqL = (const int*)d_in[1];
    const float* Wm   = (const float*)d_in[2];
    const float* p    = (const float*)d_in[3];
    float* out = (float*)d_out;

    seg_max_kernel<<<B_SEG * C_DIM, 192>>>(x, seqL);

    dim3 grid2(O_DIM / OTILE, B_SEG);
    conv_gem_kernel<<<grid2, 192>>>(Wm, p, out);
}

// round 2
// speedup vs baseline: 1.3982x; 1.3982x over previous
#include <cuda_runtime.h>
#include <math.h>

#define C_DIM 128
#define S_DIM 4096
#define HW 176          // 16 * 11
#define HW4 44          // HW / 4
#define B_SEG 32
#define O_DIM 256
#define OTILE 16
#define CCHUNK 32
#define PART_LEN 44     // 4 rows * 11
#define GEM_EPS 1e-6f
#define NEG_INF -3.402823466e38f

// scratch: pooled[b][c][hw]
__device__ float g_pooled[B_SEG * C_DIM * HW];

__device__ __forceinline__ float4 max4(float4 a, float4 b) {
    float4 r;
    r.x = fmaxf(a.x, b.x); r.y = fmaxf(a.y, b.y);
    r.z = fmaxf(a.z, b.z); r.w = fmaxf(a.w, b.w);
    return r;
}

// packed fp32x2 helpers (Blackwell FFMA2 path)
__device__ __forceinline__ unsigned long long pack2(float lo, float hi) {
    unsigned long long r;
    asm("mov.b64 %0, {%1, %2};" : "=l"(r) : "f"(lo), "f"(hi));
    return r;
}
__device__ __forceinline__ void unpack2(unsigned long long v, float& lo, float& hi) {
    asm("mov.b64 {%0, %1}, %2;" : "=f"(lo), "=f"(hi) : "l"(v));
}
__device__ __forceinline__ void ffma2(unsigned long long& d,
                                      unsigned long long a, unsigned long long b) {
    asm("fma.rn.f32x2 %0, %1, %2, %0;" : "+l"(d) : "l"(a), "l"(b));
}

// ---------------------------------------------------------------------------
// Kernel 1: ragged segment max, float4 streaming.
// One block per (b, c); region x[c, s0:s1, :, :] is contiguous (len*176 floats
// = len*44 float4). 352 threads = 8 s-groups x 44 f4-columns; each thread
// scans frames s = sg, sg+8, ... with 4-way unroll (MLP=4 x 16B).
// ---------------------------------------------------------------------------
__global__ void __launch_bounds__(352) seg_max_kernel(
    const float* __restrict__ x, const int* __restrict__ seqL)
{
    int blk = blockIdx.x;
    int b = blk & (B_SEG - 1);
    int c = blk >> 5;

    __shared__ int sh[2];
    __shared__ float4 sm[8 * HW4];

    if (threadIdx.x == 0) {
        int s0 = 0;
        #pragma unroll
        for (int i = 0; i < B_SEG; i++) s0 += (i < b) ? seqL[i] : 0;
        sh[0] = s0;
        sh[1] = seqL[b];
    }
    __syncthreads();

    int tid = threadIdx.x;
    int sg  = tid / HW4;   // 0..7
    int col = tid % HW4;   // 0..43

    int s0  = sh[0];
    int len = sh[1];

    const float4* bp = reinterpret_cast<const float4*>(x)
                     + (size_t)c * (S_DIM * HW4) + (size_t)s0 * HW4 + col;

    float4 m = make_float4(NEG_INF, NEG_INF, NEG_INF, NEG_INF);
    int s = sg;
    for (; s + 24 < len; s += 32) {
        float4 a0 = bp[(size_t)(s +  0) * HW4];
        float4 a1 = bp[(size_t)(s +  8) * HW4];
        float4 a2 = bp[(size_t)(s + 16) * HW4];
        float4 a3 = bp[(size_t)(s + 24) * HW4];
        m = max4(m, max4(max4(a0, a1), max4(a2, a3)));
    }
    for (; s < len; s += 8) {
        m = max4(m, bp[(size_t)s * HW4]);
    }

    sm[sg * HW4 + col] = m;
    __syncthreads();

    if (tid < HW4) {
        float4 r = sm[tid];
        #pragma unroll
        for (int g = 1; g < 8; g++) r = max4(r, sm[g * HW4 + tid]);
        reinterpret_cast<float4*>(g_pooled)[(size_t)(b * C_DIM + c) * HW4 + tid] = r;
    }
}

// ---------------------------------------------------------------------------
// Kernel 2: fused 1x1 conv (FFMA2) + GeM.
// Grid (16 o-tiles, 32 b), 192 threads. pooled staged through smem in 4
// chunks of 32 channels; W tile resident in smem as [c][16 o] rows read as
// u64 pairs. Thread hw holds 8 packed accumulators (16 o-channels).
// ---------------------------------------------------------------------------
__global__ void __launch_bounds__(192) conv_gem_kernel(
    const float* __restrict__ Wmat, const float* __restrict__ p,
    float* __restrict__ out)
{
    __shared__ __align__(16) float ws[C_DIM * OTILE];   // [c][j], 8 KB
    __shared__ __align__(16) float pch[CCHUNK * HW];    // [cc][hw], 22 KB
    __shared__ float pp[4];

    int b   = blockIdx.y;
    int o0  = blockIdx.x * OTILE;
    int tid = threadIdx.x;
    int hw  = tid;

    if (tid < 4) pp[tid] = p[tid];
    for (int i = tid; i < C_DIM * OTILE; i += 192) {
        int cc = i >> 4;
        int j  = i & (OTILE - 1);
        ws[i] = Wmat[(o0 + j) * C_DIM + cc];
    }
    __syncthreads();

    unsigned long long acc[OTILE / 2];
    #pragma unroll
    for (int k = 0; k < OTILE / 2; k++) acc[k] = 0ULL;

    const float4* gp4 = reinterpret_cast<const float4*>(g_pooled)
                      + (size_t)b * (C_DIM * HW4);

    for (int c0 = 0; c0 < C_DIM; c0 += CCHUNK) {
        // cooperative load of pooled[b, c0:c0+32, :] (1408 float4)
        for (int i = tid; i < CCHUNK * HW4; i += 192) {
            reinterpret_cast<float4*>(pch)[i] = gp4[(size_t)c0 * HW4 + i];
        }
        __syncthreads();

        if (hw < HW) {
            #pragma unroll 4
            for (int ccl = 0; ccl < CCHUNK; ccl++) {
                float pv = pch[ccl * HW + hw];
                unsigned long long pv2 = pack2(pv, pv);
                const ulonglong2* wr = reinterpret_cast<const ulonglong2*>(
                    ws + (c0 + ccl) * OTILE);
                #pragma unroll
                for (int q = 0; q < OTILE / 4; q++) {
                    ulonglong2 w = wr[q];
                    ffma2(acc[q * 2 + 0], pv2, w.x);
                    ffma2(acc[q * 2 + 1], pv2, w.y);
                }
            }
        }
        __syncthreads();
    }

    // GeM elementwise power into smem (reuse pch as ypow[16][176])
    float* ypow = pch;
    if (hw < HW) {
        int part = hw / PART_LEN;
        float pe = pp[part];
        #pragma unroll
        for (int k = 0; k < OTILE / 2; k++) {
            float lo, hi;
            unpack2(acc[k], lo, hi);
            float v0 = fmaxf(lo, GEM_EPS);
            float v1 = fmaxf(hi, GEM_EPS);
            ypow[(2 * k + 0) * HW + hw] = exp2f(pe * __log2f(v0));
            ypow[(2 * k + 1) * HW + hw] = exp2f(pe * __log2f(v1));
        }
    }
    __syncthreads();

    // 64 threads: one per (o, part)
    if (tid < OTILE * 4) {
        int j    = tid >> 2;
        int part = tid & 3;
        const float* yp = ypow + j * HW + part * PART_LEN;
        float sum = 0.0f;
        #pragma unroll
        for (int k = 0; k < PART_LEN; k++) sum += yp[k];
        float pe = pp[part];
        float mean = sum * (1.0f / (float)PART_LEN);
        float g = (mean > 0.0f) ? exp2f(__log2f(mean) / pe) : 0.0f;
        out[((size_t)b * O_DIM + o0 + j) * 4 + part] = g;
    }
}

extern "C" void kernel_launch(void* const* d_in, const int* in_sizes, int n_in,
                              void* d_out, int out_size)
{
    const float* x    = (const float*)d_in[0];
    const int*   seqL = (const int*)d_in[1];
    const float* Wm   = (const float*)d_in[2];
    const float* p    = (const float*)d_in[3];
    float* out = (float*)d_out;

    seg_max_kernel<<<B_SEG * C_DIM, 352>>>(x, seqL);

    dim3 grid2(O_DIM / OTILE, B_SEG);
    conv_gem_kernel<<<grid2, 192>>>(Wm, p, out);
}

// round 3
// speedup vs baseline: 1.4391x; 1.0292x over previous
#include <cuda_runtime.h>
#include <math.h>

#define C_DIM 128
#define S_DIM 4096
#define HW 176          // 16 * 11
#define HW4 44          // HW / 4
#define B_SEG 32
#define O_DIM 256
#define OTILE 16
#define PART_LEN 44     // 4 rows * 11
#define GEM_EPS 1e-6f
#define NEG_INF -3.402823466e38f

// scratch: pooled[b][c][hw]
__device__ float g_pooled[B_SEG * C_DIM * HW];

__device__ __forceinline__ float4 max4(float4 a, float4 b) {
    float4 r;
    r.x = fmaxf(a.x, b.x); r.y = fmaxf(a.y, b.y);
    r.z = fmaxf(a.z, b.z); r.w = fmaxf(a.w, b.w);
    return r;
}

// packed fp32x2 helpers (Blackwell FFMA2 path)
__device__ __forceinline__ unsigned long long pack2(float lo, float hi) {
    unsigned long long r;
    asm("mov.b64 %0, {%1, %2};" : "=l"(r) : "f"(lo), "f"(hi));
    return r;
}
__device__ __forceinline__ void unpack2(unsigned long long v, float& lo, float& hi) {
    asm("mov.b64 {%0, %1}, %2;" : "=f"(lo), "=f"(hi) : "l"(v));
}
__device__ __forceinline__ void ffma2(unsigned long long& d,
                                      unsigned long long a, unsigned long long b) {
    asm("fma.rn.f32x2 %0, %1, %2, %0;" : "+l"(d) : "l"(a), "l"(b));
}

// ---------------------------------------------------------------------------
// Kernel 1: ragged segment max, float4 streaming with evict-first loads.
// One block per (b, c); 352 threads = 8 s-groups x 44 f4-columns.
// ---------------------------------------------------------------------------
__global__ void __launch_bounds__(352) seg_max_kernel(
    const float* __restrict__ x, const int* __restrict__ seqL)
{
    int blk = blockIdx.x;
    int b = blk & (B_SEG - 1);
    int c = blk >> 5;

    __shared__ int sh[2];
    __shared__ float4 sm[8 * HW4];

    if (threadIdx.x == 0) {
        int s0 = 0;
        #pragma unroll
        for (int i = 0; i < B_SEG; i++) s0 += (i < b) ? seqL[i] : 0;
        sh[0] = s0;
        sh[1] = seqL[b];
    }
    __syncthreads();

    int tid = threadIdx.x;
    int sg  = tid / HW4;   // 0..7
    int col = tid % HW4;   // 0..43

    int s0  = sh[0];
    int len = sh[1];

    const float4* bp = reinterpret_cast<const float4*>(x)
                     + (size_t)c * (S_DIM * HW4) + (size_t)s0 * HW4 + col;

    float4 m = make_float4(NEG_INF, NEG_INF, NEG_INF, NEG_INF);
    int s = sg;
    for (; s + 24 < len; s += 32) {
        float4 a0 = __ldcs(&bp[(size_t)(s +  0) * HW4]);
        float4 a1 = __ldcs(&bp[(size_t)(s +  8) * HW4]);
        float4 a2 = __ldcs(&bp[(size_t)(s + 16) * HW4]);
        float4 a3 = __ldcs(&bp[(size_t)(s + 24) * HW4]);
        m = max4(m, max4(max4(a0, a1), max4(a2, a3)));
    }
    for (; s < len; s += 8) {
        m = max4(m, __ldcs(&bp[(size_t)s * HW4]));
    }

    sm[sg * HW4 + col] = m;
    __syncthreads();

    if (tid < HW4) {
        float4 r = sm[tid];
        #pragma unroll
        for (int g = 1; g < 8; g++) r = max4(r, sm[g * HW4 + tid]);
        reinterpret_cast<float4*>(g_pooled)[(size_t)(b * C_DIM + c) * HW4 + tid] = r;
    }
}

// ---------------------------------------------------------------------------
// Kernel 2: fused 1x1 conv (FFMA2) + GeM, no pooled staging.
// Grid (16 o-tiles, 32 b), 96 threads. Thread t owns hw = {2t, 2t+1}
// (t < 88), reading pooled directly as float2 from L2. W tile resident in
// smem as [c][16 o], read as broadcast LDS.128. Accumulators: 8 packed
// o-pairs per hw (16 u64 regs total).
// ---------------------------------------------------------------------------
__global__ void __launch_bounds__(96) conv_gem_kernel(
    const float* __restrict__ Wmat, const float* __restrict__ p,
    float* __restrict__ out)
{
    __shared__ __align__(16) float ws[C_DIM * OTILE];   // [c][j], 8 KB
    __shared__ float ypow[OTILE * HW];                  // [j][hw], 11 KB
    __shared__ float pp[4];

    int b   = blockIdx.y;
    int o0  = blockIdx.x * OTILE;
    int tid = threadIdx.x;

    if (tid < 4) pp[tid] = p[tid];
    for (int i = tid; i < C_DIM * OTILE; i += 96) {
        int cc = i >> 4;
        int j  = i & (OTILE - 1);
        ws[i] = Wmat[(o0 + j) * C_DIM + cc];
    }
    __syncthreads();

    if (tid < HW / 2) {
        unsigned long long accA[OTILE / 2];   // hw0, o-pairs
        unsigned long long accB[OTILE / 2];   // hw1, o-pairs
        #pragma unroll
        for (int k = 0; k < OTILE / 2; k++) { accA[k] = 0ULL; accB[k] = 0ULL; }

        const float2* pb = reinterpret_cast<const float2*>(
            g_pooled + (size_t)b * C_DIM * HW) + tid;

        #pragma unroll 4
        for (int cc = 0; cc < C_DIM; cc++) {
            float2 pv = __ldg(&pb[(size_t)cc * (HW / 2)]);
            unsigned long long pvA = pack2(pv.x, pv.x);
            unsigned long long pvB = pack2(pv.y, pv.y);
            const ulonglong2* wr = reinterpret_cast<const ulonglong2*>(
                ws + cc * OTILE);
            #pragma unroll
            for (int q = 0; q < OTILE / 4; q++) {
                ulonglong2 w = wr[q];
                ffma2(accA[q * 2 + 0], pvA, w.x);
                ffma2(accA[q * 2 + 1], pvA, w.y);
                ffma2(accB[q * 2 + 0], pvB, w.x);
                ffma2(accB[q * 2 + 1], pvB, w.y);
            }
        }

        // GeM elementwise power into smem. hw0=2t, hw1=2t+1 share a part
        // (part boundaries are multiples of 44, even).
        int hw0 = 2 * tid;
        float pe = pp[hw0 / PART_LEN];
        #pragma unroll
        for (int k = 0; k < OTILE / 2; k++) {
            float a0, a1, b0, b1;
            unpack2(accA[k], a0, a1);
            unpack2(accB[k], b0, b1);
            ypow[(2 * k + 0) * HW + hw0]     = exp2f(pe * __log2f(fmaxf(a0, GEM_EPS)));
            ypow[(2 * k + 1) * HW + hw0]     = exp2f(pe * __log2f(fmaxf(a1, GEM_EPS)));
            ypow[(2 * k + 0) * HW + hw0 + 1] = exp2f(pe * __log2f(fmaxf(b0, GEM_EPS)));
            ypow[(2 * k + 1) * HW + hw0 + 1] = exp2f(pe * __log2f(fmaxf(b1, GEM_EPS)));
        }
    }
    __syncthreads();

    // 64 threads: one per (o, part)
    if (tid < OTILE * 4) {
        int j    = tid >> 2;
        int part = tid & 3;
        const float* yp = ypow + j * HW + part * PART_LEN;
        float sum = 0.0f;
        #pragma unroll
        for (int k = 0; k < PART_LEN; k++) sum += yp[k];
        float pe = pp[part];
        float mean = sum * (1.0f / (float)PART_LEN);
        float g = (mean > 0.0f) ? exp2f(__log2f(mean) / pe) : 0.0f;
        out[((size_t)b * O_DIM + o0 + j) * 4 + part] = g;
    }
}

extern "C" void kernel_launch(void* const* d_in, const int* in_sizes, int n_in,
                              void* d_out, int out_size)
{
    const float* x    = (const float*)d_in[0];
    const int*   seqL = (const int*)d_in[1];
    const float* Wm   = (const float*)d_in[2];
    const float* p    = (const float*)d_in[3];
    float* out = (float*)d_out;

    seg_max_kernel<<<B_SEG * C_DIM, 352>>>(x, seqL);

    dim3 grid2(O_DIM / OTILE, B_SEG);
    conv_gem_kernel<<<grid2, 96>>>(Wm, p, out);
}

// round 4
// speedup vs baseline: 1.4686x; 1.0205x over previous
#include <cuda_runtime.h>
#include <math.h>

#define C_DIM 128
#define S_DIM 4096
#define HW 176          // 16 * 11
#define HW4 44          // HW / 4
#define B_SEG 32
#define O_DIM 256
#define OTILE 16
#define PART_LEN 44     // 4 rows * 11
#define GEM_EPS 1e-6f
#define NEG_INF -3.402823466e38f

// scratch: pooled[b][c][hw]
__device__ float g_pooled[B_SEG * C_DIM * HW];

__device__ __forceinline__ float4 max4(float4 a, float4 b) {
    float4 r;
    r.x = fmaxf(a.x, b.x); r.y = fmaxf(a.y, b.y);
    r.z = fmaxf(a.z, b.z); r.w = fmaxf(a.w, b.w);
    return r;
}

// packed fp32x2 helpers (Blackwell FFMA2 path)
__device__ __forceinline__ unsigned long long pack2(float v) {
    unsigned long long r;
    asm("mov.b64 %0, {%1, %1};" : "=l"(r) : "f"(v));
    return r;
}
__device__ __forceinline__ void unpack2(unsigned long long v, float& lo, float& hi) {
    asm("mov.b64 {%0, %1}, %2;" : "=f"(lo), "=f"(hi) : "l"(v));
}
__device__ __forceinline__ void ffma2(unsigned long long& d,
                                      unsigned long long a, unsigned long long b) {
    asm("fma.rn.f32x2 %0, %1, %2, %0;" : "+l"(d) : "l"(a), "l"(b));
}

// ---------------------------------------------------------------------------
// Kernel 1: ragged segment max, float4 streaming with evict-first loads.
// One block per (b, c); 352 threads = 8 s-groups x 44 f4-columns.
// AT HBM ROOFLINE — do not touch.
// ---------------------------------------------------------------------------
__global__ void __launch_bounds__(352) seg_max_kernel(
    const float* __restrict__ x, const int* __restrict__ seqL)
{
    int blk = blockIdx.x;
    int b = blk & (B_SEG - 1);
    int c = blk >> 5;

    __shared__ int sh[2];
    __shared__ float4 sm[8 * HW4];

    if (threadIdx.x == 0) {
        int s0 = 0;
        #pragma unroll
        for (int i = 0; i < B_SEG; i++) s0 += (i < b) ? seqL[i] : 0;
        sh[0] = s0;
        sh[1] = seqL[b];
    }
    __syncthreads();

    int tid = threadIdx.x;
    int sg  = tid / HW4;   // 0..7
    int col = tid % HW4;   // 0..43

    int s0  = sh[0];
    int len = sh[1];

    const float4* bp = reinterpret_cast<const float4*>(x)
                     + (size_t)c * (S_DIM * HW4) + (size_t)s0 * HW4 + col;

    float4 m = make_float4(NEG_INF, NEG_INF, NEG_INF, NEG_INF);
    int s = sg;
    for (; s + 24 < len; s += 32) {
        float4 a0 = __ldcs(&bp[(size_t)(s +  0) * HW4]);
        float4 a1 = __ldcs(&bp[(size_t)(s +  8) * HW4]);
        float4 a2 = __ldcs(&bp[(size_t)(s + 16) * HW4]);
        float4 a3 = __ldcs(&bp[(size_t)(s + 24) * HW4]);
        m = max4(m, max4(max4(a0, a1), max4(a2, a3)));
    }
    for (; s < len; s += 8) {
        m = max4(m, __ldcs(&bp[(size_t)s * HW4]));
    }

    sm[sg * HW4 + col] = m;
    __syncthreads();

    if (tid < HW4) {
        float4 r = sm[tid];
        #pragma unroll
        for (int g = 1; g < 8; g++) r = max4(r, sm[g * HW4 + tid]);
        reinterpret_cast<float4*>(g_pooled)[(size_t)(b * C_DIM + c) * HW4 + tid] = r;
    }
}

// ---------------------------------------------------------------------------
// Kernel 2: fused 1x1 conv (FFMA2) + GeM.
// Grid (16 o-tiles, 32 b) = 512 blocks, 192 threads (6 warps) for latency
// hiding. Thread = 1 hw (176 active). Per cc: 1 coalesced LDG.32 of pooled,
// 4 broadcast LDS.128 of the W tile, 8 FFMA2 (o-pairs). Unroll 8 -> MLP 8.
// ---------------------------------------------------------------------------
__global__ void __launch_bounds__(192) conv_gem_kernel(
    const float* __restrict__ Wmat, const float* __restrict__ p,
    float* __restrict__ out)
{
    __shared__ __align__(16) float ws[C_DIM * OTILE];   // [c][j], 8 KB
    __shared__ float ypow[OTILE * HW];                  // [j][hw], 11 KB
    __shared__ float pp[4];

    int b   = blockIdx.y;
    int o0  = blockIdx.x * OTILE;
    int tid = threadIdx.x;
    int hw  = tid;

    if (tid < 4) pp[tid] = p[tid];
    for (int i = tid; i < C_DIM * OTILE; i += 192) {
        int cc = i >> 4;
        int j  = i & (OTILE - 1);
        ws[i] = Wmat[(o0 + j) * C_DIM + cc];
    }
    __syncthreads();

    if (hw < HW) {
        unsigned long long acc[OTILE / 2];
        #pragma unroll
        for (int k = 0; k < OTILE / 2; k++) acc[k] = 0ULL;

        const float* pb = g_pooled + (size_t)b * C_DIM * HW + hw;

        #pragma unroll 8
        for (int cc = 0; cc < C_DIM; cc++) {
            unsigned long long pv2 = pack2(__ldg(&pb[(size_t)cc * HW]));
            const ulonglong2* wr = reinterpret_cast<const ulonglong2*>(
                ws + cc * OTILE);
            #pragma unroll
            for (int q = 0; q < OTILE / 4; q++) {
                ulonglong2 w = wr[q];
                ffma2(acc[q * 2 + 0], pv2, w.x);
                ffma2(acc[q * 2 + 1], pv2, w.y);
            }
        }

        int part = hw / PART_LEN;
        float pe = pp[part];
        #pragma unroll
        for (int k = 0; k < OTILE / 2; k++) {
            float lo, hi;
            unpack2(acc[k], lo, hi);
            ypow[(2 * k + 0) * HW + hw] = exp2f(pe * __log2f(fmaxf(lo, GEM_EPS)));
            ypow[(2 * k + 1) * HW + hw] = exp2f(pe * __log2f(fmaxf(hi, GEM_EPS)));
        }
    }
    __syncthreads();

    // 64 threads: one per (o, part)
    if (tid < OTILE * 4) {
        int j    = tid >> 2;
        int part = tid & 3;
        const float* yp = ypow + j * HW + part * PART_LEN;
        float sum = 0.0f;
        #pragma unroll
        for (int k = 0; k < PART_LEN; k++) sum += yp[k];
        float pe = pp[part];
        float mean = sum * (1.0f / (float)PART_LEN);
        float g = (mean > 0.0f) ? exp2f(__log2f(mean) / pe) : 0.0f;
        out[((size_t)b * O_DIM + o0 + j) * 4 + part] = g;
    }
}

extern "C" void kernel_launch(void* const* d_in, const int* in_sizes, int n_in,
                              void* d_out, int out_size)
{
    const float* x    = (const float*)d_in[0];
    const int*   seqL = (const int*)d_in[1];
    const float* Wm   = (const float*)d_in[2];
    const float* p    = (const float*)d_in[3];
    float* out = (float*)d_out;

    seg_max_kernel<<<B_SEG * C_DIM, 352>>>(x, seqL);

    dim3 grid2(O_DIM / OTILE, B_SEG);
    conv_gem_kernel<<<grid2, 192>>>(Wm, p, out);
}

// round 5
// speedup vs baseline: 1.4720x; 1.0023x over previous
#include <cuda_runtime.h>
#include <math.h>

#define C_DIM 128
#define S_DIM 4096
#define HW 176          // 16 * 11
#define HW4 44          // HW / 4
#define B_SEG 32
#define O_DIM 256
#define OTILE 8
#define PART_LEN 44     // 4 rows * 11
#define GEM_EPS 1e-6f
#define NEG_INF -3.402823466e38f

// scratch: pooled[b][c][hw]
__device__ float g_pooled[B_SEG * C_DIM * HW];

__device__ __forceinline__ float4 max4(float4 a, float4 b) {
    float4 r;
    r.x = fmaxf(a.x, b.x); r.y = fmaxf(a.y, b.y);
    r.z = fmaxf(a.z, b.z); r.w = fmaxf(a.w, b.w);
    return r;
}

// packed fp32x2 helpers (Blackwell FFMA2 path)
__device__ __forceinline__ unsigned long long pack2(float v) {
    unsigned long long r;
    asm("mov.b64 %0, {%1, %1};" : "=l"(r) : "f"(v));
    return r;
}
__device__ __forceinline__ void unpack2(unsigned long long v, float& lo, float& hi) {
    asm("mov.b64 {%0, %1}, %2;" : "=f"(lo), "=f"(hi) : "l"(v));
}
__device__ __forceinline__ void ffma2(unsigned long long& d,
                                      unsigned long long a, unsigned long long b) {
    asm("fma.rn.f32x2 %0, %1, %2, %0;" : "+l"(d) : "l"(a), "l"(b));
}

// ---------------------------------------------------------------------------
// Kernel 1: ragged segment max, float4 streaming, evict-first, MLP=8.
// One block per (b, c); 352 threads = 8 s-groups x 44 f4-columns.
// ---------------------------------------------------------------------------
__global__ void __launch_bounds__(352) seg_max_kernel(
    const float* __restrict__ x, const int* __restrict__ seqL)
{
    int blk = blockIdx.x;
    int b = blk & (B_SEG - 1);
    int c = blk >> 5;

    __shared__ int sh[2];
    __shared__ float4 sm[8 * HW4];

    if (threadIdx.x == 0) {
        int s0 = 0;
        #pragma unroll
        for (int i = 0; i < B_SEG; i++) s0 += (i < b) ? seqL[i] : 0;
        sh[0] = s0;
        sh[1] = seqL[b];
    }
    __syncthreads();

    int tid = threadIdx.x;
    int sg  = tid / HW4;   // 0..7
    int col = tid % HW4;   // 0..43

    int s0  = sh[0];
    int len = sh[1];

    const float4* bp = reinterpret_cast<const float4*>(x)
                     + (size_t)c * (S_DIM * HW4) + (size_t)s0 * HW4 + col;

    float4 m = make_float4(NEG_INF, NEG_INF, NEG_INF, NEG_INF);
    int s = sg;
    for (; s + 56 < len; s += 64) {
        float4 a0 = __ldcs(&bp[(size_t)(s +  0) * HW4]);
        float4 a1 = __ldcs(&bp[(size_t)(s +  8) * HW4]);
        float4 a2 = __ldcs(&bp[(size_t)(s + 16) * HW4]);
        float4 a3 = __ldcs(&bp[(size_t)(s + 24) * HW4]);
        float4 a4 = __ldcs(&bp[(size_t)(s + 32) * HW4]);
        float4 a5 = __ldcs(&bp[(size_t)(s + 40) * HW4]);
        float4 a6 = __ldcs(&bp[(size_t)(s + 48) * HW4]);
        float4 a7 = __ldcs(&bp[(size_t)(s + 56) * HW4]);
        m = max4(m, max4(max4(max4(a0, a1), max4(a2, a3)),
                         max4(max4(a4, a5), max4(a6, a7))));
    }
    for (; s < len; s += 8) {
        m = max4(m, __ldcs(&bp[(size_t)s * HW4]));
    }

    sm[sg * HW4 + col] = m;
    __syncthreads();

    if (tid < HW4) {
        float4 r = sm[tid];
        #pragma unroll
        for (int g = 1; g < 8; g++) r = max4(r, sm[g * HW4 + tid]);
        reinterpret_cast<float4*>(g_pooled)[(size_t)(b * C_DIM + c) * HW4 + tid] = r;
    }
}

// ---------------------------------------------------------------------------
// Kernel 2: fused 1x1 conv (FFMA2) + GeM.
// Grid (32 o-tiles of 8, 32 b) = 1024 blocks, 192 threads.
// Per cc per thread: 1 LDG.32 (coalesced) + 1 mov + 2 broadcast LDS.128 +
// 4 FFMA2. acc = 4 u64 regs -> high occupancy.
// ---------------------------------------------------------------------------
__global__ void __launch_bounds__(192) conv_gem_kernel(
    const float* __restrict__ Wmat, const float* __restrict__ p,
    float* __restrict__ out)
{
    __shared__ __align__(16) float ws[C_DIM * OTILE];   // [c][j], 4 KB
    __shared__ float ypow[OTILE * HW];                  // [j][hw], 5.5 KB
    __shared__ float pp[4];

    int b   = blockIdx.y;
    int o0  = blockIdx.x * OTILE;
    int tid = threadIdx.x;
    int hw  = tid;

    if (tid < 4) pp[tid] = p[tid];
    for (int i = tid; i < C_DIM * OTILE; i += 192) {
        int cc = i >> 3;
        int j  = i & (OTILE - 1);
        ws[i] = Wmat[(o0 + j) * C_DIM + cc];
    }
    __syncthreads();

    if (hw < HW) {
        unsigned long long acc[OTILE / 2];
        #pragma unroll
        for (int k = 0; k < OTILE / 2; k++) acc[k] = 0ULL;

        const float* pb = g_pooled + (size_t)b * C_DIM * HW + hw;

        #pragma unroll 8
        for (int cc = 0; cc < C_DIM; cc++) {
            unsigned long long pv2 = pack2(__ldg(&pb[(size_t)cc * HW]));
            const ulonglong2* wr = reinterpret_cast<const ulonglong2*>(
                ws + cc * OTILE);
            ulonglong2 w0 = wr[0];
            ulonglong2 w1 = wr[1];
            ffma2(acc[0], pv2, w0.x);
            ffma2(acc[1], pv2, w0.y);
            ffma2(acc[2], pv2, w1.x);
            ffma2(acc[3], pv2, w1.y);
        }

        int part = hw / PART_LEN;
        float pe = pp[part];
        #pragma unroll
        for (int k = 0; k < OTILE / 2; k++) {
            float lo, hi;
            unpack2(acc[k], lo, hi);
            ypow[(2 * k + 0) * HW + hw] = exp2f(pe * __log2f(fmaxf(lo, GEM_EPS)));
            ypow[(2 * k + 1) * HW + hw] = exp2f(pe * __log2f(fmaxf(hi, GEM_EPS)));
        }
    }
    __syncthreads();

    // 32 threads: one per (o, part)
    if (tid < OTILE * 4) {
        int j    = tid >> 2;
        int part = tid & 3;
        const float* yp = ypow + j * HW + part * PART_LEN;
        float sum = 0.0f;
        #pragma unroll
        for (int k = 0; k < PART_LEN; k++) sum += yp[k];
        float pe = pp[part];
        float mean = sum * (1.0f / (float)PART_LEN);
        float g = (mean > 0.0f) ? exp2f(__log2f(mean) / pe) : 0.0f;
        out[((size_t)b * O_DIM + o0 + j) * 4 + part] = g;
    }
}

extern "C" void kernel_launch(void* const* d_in, const int* in_sizes, int n_in,
                              void* d_out, int out_size)
{
    const float* x    = (const float*)d_in[0];
    const int*   seqL = (const int*)d_in[1];
    const float* Wm   = (const float*)d_in[2];
    const float* p    = (const float*)d_in[3];
    float* out = (float*)d_out;

    seg_max_kernel<<<B_SEG * C_DIM, 352>>>(x, seqL);

    dim3 grid2(O_DIM / OTILE, B_SEG);
    conv_gem_kernel<<<grid2, 192>>>(Wm, p, out);
}